// round 2
// baseline (speedup 1.0000x reference)
#include <cuda_runtime.h>

#define TT 25
#define BB 4096
#define INP 500
#define HH 64
#define GG 256   // 4*H
#define NL 25
#define RPB 32       // rows per block
#define NTHR 256
#define WST 260      // padded shared W row stride (floats)

// scratch (sanctioned: __device__ globals, no runtime allocation)
__device__ float g_xp0[(size_t)TT * BB * GG];          // 100 MB: layer-0 input projection
__device__ float g_hs[2][(size_t)TT * BB * HH];        // ping-pong layer outputs

__device__ __forceinline__ float sigf(float x) {
    return __fdividef(1.0f, 1.0f + __expf(-x));
}
__device__ __forceinline__ float tanhf_fast(float x) {
    // 1 - 2/(e^{2x}+1): saturates correctly at +-inf, ~1e-6 rel err
    return 1.0f - __fdividef(2.0f, __expf(2.0f * x) + 1.0f);
}

// ---------------------------------------------------------------------------
// Layer-0 input projection: xp0[t*B+b][g] = sum_k x[t,b,k]*Wih0[g][k] + bih0[g]+bhh0[g]
// ---------------------------------------------------------------------------
__global__ void __launch_bounds__(NTHR)
proj0_kernel(const float* __restrict__ x, const float* __restrict__ W,
             const float* __restrict__ bih, const float* __restrict__ bhh)
{
    extern __shared__ float sm[];
    float* shW = sm;                 // [64][WST]
    float* shX = sm + 64 * WST;      // [32][64]
    const int tid  = threadIdx.x;
    const int lane = tid & 31;
    const int w    = tid >> 5;
    const int rowBase = blockIdx.x * RPB;

    float acc[4][8];
#pragma unroll
    for (int j = 0; j < 8; ++j) {
        int g = lane + 32 * j;
        float b = bih[g] + bhh[g];
#pragma unroll
        for (int r = 0; r < 4; ++r) acc[r][j] = b;
    }

    for (int k0 = 0; k0 < INP; k0 += 64) {
        for (int idx = tid; idx < 64 * GG; idx += NTHR) {
            int kk = idx & 63, g = idx >> 6;
            float v = (k0 + kk < INP) ? W[(size_t)g * INP + k0 + kk] : 0.0f;
            shW[kk * WST + g] = v;
        }
        for (int idx = tid; idx < RPB * 64; idx += NTHR) {
            int kk = idx & 63, r = idx >> 6;
            float v = (k0 + kk < INP) ? x[(size_t)(rowBase + r) * INP + k0 + kk] : 0.0f;
            shX[r * 64 + kk] = v;
        }
        __syncthreads();
#pragma unroll 4
        for (int k = 0; k < 64; ++k) {
            float wv[8];
#pragma unroll
            for (int j = 0; j < 8; ++j) wv[j] = shW[k * WST + lane + 32 * j];
#pragma unroll
            for (int r = 0; r < 4; ++r) {
                float xv = shX[(4 * w + r) * 64 + k];
#pragma unroll
                for (int j = 0; j < 8; ++j) acc[r][j] += xv * wv[j];
            }
        }
        __syncthreads();
    }
#pragma unroll
    for (int r = 0; r < 4; ++r) {
        size_t rb = (size_t)(rowBase + 4 * w + r) * GG;
#pragma unroll
        for (int j = 0; j < 8; ++j) g_xp0[rb + lane + 32 * j] = acc[r][j];
    }
}

// ---------------------------------------------------------------------------
// Layer 0 recurrence: gates = xp0[t] + h @ Whh^T ; writes g_hs[0], h_n[0], c_n[0]
// ---------------------------------------------------------------------------
__global__ void __launch_bounds__(NTHR)
layer0_kernel(const float* __restrict__ Whh,
              float* __restrict__ out_hn, float* __restrict__ out_cn)
{
    extern __shared__ float sm[];
    float* shW = sm;                 // [64][WST]
    float* shH = sm + 64 * WST;      // [32][64]
    const int tid  = threadIdx.x;
    const int lane = tid & 31;
    const int w    = tid >> 5;
    const int rowBase = blockIdx.x * RPB;

    for (int idx = tid; idx < 64 * GG; idx += NTHR) {
        int kk = idx & 63, g = idx >> 6;
        shW[kk * WST + g] = Whh[g * HH + kk];
    }
    for (int idx = tid; idx < RPB * HH; idx += NTHR) shH[idx] = 0.0f;
    __syncthreads();

    float c0[4] = {0, 0, 0, 0}, c1[4] = {0, 0, 0, 0};

    for (int t = 0; t < TT; ++t) {
        float acc[4][8];
#pragma unroll
        for (int r = 0; r < 4; ++r) {
            size_t base = ((size_t)t * BB + rowBase + 4 * w + r) * GG;
#pragma unroll
            for (int j = 0; j < 8; ++j) acc[r][j] = g_xp0[base + lane + 32 * j];
        }
#pragma unroll 4
        for (int k = 0; k < HH; ++k) {
            float wv[8];
#pragma unroll
            for (int j = 0; j < 8; ++j) wv[j] = shW[k * WST + lane + 32 * j];
#pragma unroll
            for (int r = 0; r < 4; ++r) {
                float hv = shH[(4 * w + r) * HH + k];
#pragma unroll
                for (int j = 0; j < 8; ++j) acc[r][j] += hv * wv[j];
            }
        }
        __syncwarp();
#pragma unroll
        for (int r = 0; r < 4; ++r) {
            float i0 = sigf(acc[r][0]), i1 = sigf(acc[r][1]);
            float f0 = sigf(acc[r][2]), f1 = sigf(acc[r][3]);
            float q0 = tanhf_fast(acc[r][4]), q1 = tanhf_fast(acc[r][5]);
            float o0 = sigf(acc[r][6]), o1 = sigf(acc[r][7]);
            c0[r] = f0 * c0[r] + i0 * q0;
            c1[r] = f1 * c1[r] + i1 * q1;
            float h0 = o0 * tanhf_fast(c0[r]);
            float h1 = o1 * tanhf_fast(c1[r]);
            shH[(4 * w + r) * HH + lane]      = h0;
            shH[(4 * w + r) * HH + lane + 32] = h1;
            size_t ob = ((size_t)t * BB + rowBase + 4 * w + r) * HH;
            g_hs[0][ob + lane]      = h0;
            g_hs[0][ob + lane + 32] = h1;
            if (t == TT - 1) {
                size_t hb = (size_t)(rowBase + 4 * w + r) * HH;
                out_hn[hb + lane] = h0;      out_hn[hb + lane + 32] = h1;
                out_cn[hb + lane] = c0[r];   out_cn[hb + lane + 32] = c1[r];
            }
        }
        __syncwarp();
    }
}

// ---------------------------------------------------------------------------
// Hidden layer l>=1: gates = bias + x_in @ Wih^T + h @ Whh^T (fused K=128 GEMM)
// ---------------------------------------------------------------------------
__global__ void __launch_bounds__(NTHR)
layer_kernel(const float* __restrict__ Wih, const float* __restrict__ Whh,
             const float* __restrict__ bih, const float* __restrict__ bhh,
             int inSel, int outSel,
             float* __restrict__ out_hn, float* __restrict__ out_cn)
{
    extern __shared__ float sm[];
    float* shW  = sm;                  // [128][WST]   rows 0..63 Wih^T, 64..127 Whh^T
    float* shXH = sm + 128 * WST;      // [32][128]    cols 0..63 x_in, 64..127 h
    const int tid  = threadIdx.x;
    const int lane = tid & 31;
    const int w    = tid >> 5;
    const int rowBase = blockIdx.x * RPB;
    const float* __restrict__ hs_in = g_hs[inSel];
    float* __restrict__ hs_out = g_hs[outSel];

    for (int idx = tid; idx < 64 * GG; idx += NTHR) {
        int kk = idx & 63, g = idx >> 6;
        shW[kk * WST + g]        = Wih[g * HH + kk];
        shW[(64 + kk) * WST + g] = Whh[g * HH + kk];
    }
    // zero h half of xh tile
    for (int idx = tid; idx < RPB * HH; idx += NTHR) {
        int r = idx >> 6, k = idx & 63;
        shXH[r * 128 + 64 + k] = 0.0f;
    }
    float bsum[8];
#pragma unroll
    for (int j = 0; j < 8; ++j) {
        int g = lane + 32 * j;
        bsum[j] = bih[g] + bhh[g];
    }
    __syncthreads();

    float c0[4] = {0, 0, 0, 0}, c1[4] = {0, 0, 0, 0};
    const int lr = lane >> 3;          // 0..3: which of my warp's rows I help load
    const int kb = (lane & 7) * 8;     // 0..56: k offset

    for (int t = 0; t < TT; ++t) {
        // per-warp load of x_in for this warp's 4 rows (no block sync needed)
        {
            size_t gb = ((size_t)t * BB + rowBase + 4 * w + lr) * HH + kb;
            float4 a = *(const float4*)&hs_in[gb];
            float4 b = *(const float4*)&hs_in[gb + 4];
            float* dst = &shXH[(4 * w + lr) * 128 + kb];
            *(float4*)dst       = a;
            *(float4*)(dst + 4) = b;
        }
        __syncwarp();

        float acc[4][8];
#pragma unroll
        for (int r = 0; r < 4; ++r)
#pragma unroll
            for (int j = 0; j < 8; ++j) acc[r][j] = bsum[j];

#pragma unroll 4
        for (int k = 0; k < 128; ++k) {
            float wv[8];
#pragma unroll
            for (int j = 0; j < 8; ++j) wv[j] = shW[k * WST + lane + 32 * j];
#pragma unroll
            for (int r = 0; r < 4; ++r) {
                float xv = shXH[(4 * w + r) * 128 + k];
#pragma unroll
                for (int j = 0; j < 8; ++j) acc[r][j] += xv * wv[j];
            }
        }
        __syncwarp();
#pragma unroll
        for (int r = 0; r < 4; ++r) {
            float i0 = sigf(acc[r][0]), i1 = sigf(acc[r][1]);
            float f0 = sigf(acc[r][2]), f1 = sigf(acc[r][3]);
            float q0 = tanhf_fast(acc[r][4]), q1 = tanhf_fast(acc[r][5]);
            float o0 = sigf(acc[r][6]), o1 = sigf(acc[r][7]);
            c0[r] = f0 * c0[r] + i0 * q0;
            c1[r] = f1 * c1[r] + i1 * q1;
            float h0 = o0 * tanhf_fast(c0[r]);
            float h1 = o1 * tanhf_fast(c1[r]);
            shXH[(4 * w + r) * 128 + 64 + lane]      = h0;
            shXH[(4 * w + r) * 128 + 64 + lane + 32] = h1;
            size_t ob = ((size_t)t * BB + rowBase + 4 * w + r) * HH;
            hs_out[ob + lane]      = h0;
            hs_out[ob + lane + 32] = h1;
            if (t == TT - 1) {
                size_t hb = (size_t)(rowBase + 4 * w + r) * HH;
                out_hn[hb + lane] = h0;      out_hn[hb + lane + 32] = h1;
                out_cn[hb + lane] = c0[r];   out_cn[hb + lane + 32] = c1[r];
            }
        }
        __syncwarp();
    }
}

// ---------------------------------------------------------------------------
// Final linear on hs[:, -1, :] (batch index B-1, faithful to reference quirk)
// ---------------------------------------------------------------------------
__global__ void final_kernel(const float* __restrict__ Wlin,
                             const float* __restrict__ blin,
                             float* __restrict__ out)
{
    int idx = threadIdx.x;
    if (idx < TT * 10) {
        int t = idx / 10, o = idx % 10;
        const float* h = &g_hs[0][((size_t)t * BB + (BB - 1)) * HH];
        float s = blin[o];
#pragma unroll
        for (int k = 0; k < HH; ++k) s += h[k] * Wlin[o * HH + k];
        out[idx] = s;
    }
}

// ---------------------------------------------------------------------------
extern "C" void kernel_launch(void* const* d_in, const int* in_sizes, int n_in,
                              void* d_out, int out_size)
{
    const float* x    = (const float*)d_in[0];
    const float* Wih0 = (const float*)d_in[1];
    const float* Whh0 = (const float*)d_in[2];
    const float* bih0 = (const float*)d_in[3];
    const float* bhh0 = (const float*)d_in[4];
    const float* WihR = (const float*)d_in[5];
    const float* WhhR = (const float*)d_in[6];
    const float* bihR = (const float*)d_in[7];
    const float* bhhR = (const float*)d_in[8];
    const float* Wlin = (const float*)d_in[9];
    const float* blin = (const float*)d_in[10];

    float* out = (float*)d_out;
    float* hn  = out + TT * 10;
    float* cn  = hn + (size_t)NL * BB * HH;

    const int SH_P  = (64 * WST + RPB * 64) * 4;     // 74752 B
    const int SH_L0 = (64 * WST + RPB * 64) * 4;     // 74752 B
    const int SH_HL = (128 * WST + RPB * 128) * 4;   // 149504 B

    cudaFuncSetAttribute(proj0_kernel,  cudaFuncAttributeMaxDynamicSharedMemorySize, SH_P);
    cudaFuncSetAttribute(layer0_kernel, cudaFuncAttributeMaxDynamicSharedMemorySize, SH_L0);
    cudaFuncSetAttribute(layer_kernel,  cudaFuncAttributeMaxDynamicSharedMemorySize, SH_HL);

    proj0_kernel<<<(TT * BB) / RPB, NTHR, SH_P>>>(x, Wih0, bih0, bhh0);
    layer0_kernel<<<BB / RPB, NTHR, SH_L0>>>(Whh0, hn, cn);

    for (int l = 1; l < NL; ++l) {
        int lr = l - 1;
        int inSel  = (l - 1) & 1;
        int outSel = l & 1;
        layer_kernel<<<BB / RPB, NTHR, SH_HL>>>(
            WihR + (size_t)lr * GG * HH, WhhR + (size_t)lr * GG * HH,
            bihR + lr * GG, bhhR + lr * GG,
            inSel, outSel,
            hn + (size_t)l * BB * HH, cn + (size_t)l * BB * HH);
    }

    final_kernel<<<1, 256>>>(Wlin, blin, out);
}